// round 2
// baseline (speedup 1.0000x reference)
#include <cuda_runtime.h>
#include <cuda_bf16.h>
#include <cstdint>

// ---------------------------------------------------------------------------
// HopfieldLayer: content = softmax(x @ wl^T * beta) @ wc^T
//   x [16384,768] f32, wl [4096,768] f32, wc [768,4096] f32 -> out [16384,768] f32
// Decomposed for bf16 precision:
//   a = expm1(beta * (x @ wl^T))                 (GEMM1, bf16 in, fp32 acc)
//   Z[r] = 4096 + sum_p a[r,p]                   (rowsum kernel)
//   out[r,d] = (colsumW[d] + (a @ wc^T)[r,d]) / Z[r]    (GEMM2)
// Engine: mma.sync.m16n8k16 bf16 (base ISA -- tcgen05 rejected by the
// harness's compute_103 virtual arch), cp.async 3-stage pipeline, ldmatrix.
// ---------------------------------------------------------------------------

#define M_ROWS 16384
#define NPROTO 4096
#define DIM    768
#define BETA_F 0.03608439182435161f

#define TILE_M 128
#define TILE_N 128
#define KC     64          // bf16 K elements per stage (128 B per smem row)

#define STAGES       3
#define STAGE_A      (TILE_M * 128)          // 16 KB
#define STAGE_B      (TILE_N * 128)          // 16 KB
#define STAGE_BYTES  (STAGE_A + STAGE_B)     // 32 KB
#define SMEM_DYN     (STAGES * STAGE_BYTES + 1024)

// ------------------------- scratch (device globals, no allocs) -------------
__device__ __align__(256) __nv_bfloat16 g_xb[(size_t)M_ROWS * DIM];
__device__ __align__(256) __nv_bfloat16 g_wl[(size_t)NPROTO * DIM];
__device__ __align__(256) __nv_bfloat16 g_wc[(size_t)DIM * NPROTO];
__device__ __align__(256) __nv_bfloat16 g_S [(size_t)M_ROWS * NPROTO];
__device__ float g_Z[M_ROWS];
__device__ float g_cs[DIM];

// ------------------------- PTX helpers -------------------------------------
static __device__ __forceinline__ uint32_t smem_u32(const void* p) {
    uint32_t a;
    asm("{ .reg .u64 t; cvta.to.shared.u64 t, %1; cvt.u32.u64 %0, t; }"
        : "=r"(a) : "l"(p));
    return a;
}

#define SWZ(o) ((o) ^ (((o) >> 3) & 0x70))

static __device__ __forceinline__ void cpasync16(uint32_t dst, const void* src) {
    asm volatile("cp.async.cg.shared.global [%0], [%1], 16;"
                 :: "r"(dst), "l"(src));
}
static __device__ __forceinline__ void cp_commit() {
    asm volatile("cp.async.commit_group;");
}
template <int N>
static __device__ __forceinline__ void cp_wait() {
    asm volatile("cp.async.wait_group %0;" :: "n"(N));
}

static __device__ __forceinline__ void ldsm4(uint32_t* r, uint32_t addr) {
    asm volatile("ldmatrix.sync.aligned.m8n8.x4.shared.b16 {%0,%1,%2,%3}, [%4];"
                 : "=r"(r[0]), "=r"(r[1]), "=r"(r[2]), "=r"(r[3])
                 : "r"(addr));
}

static __device__ __forceinline__ void mma16816(float* d, const uint32_t* a,
                                                uint32_t b0, uint32_t b1) {
    asm volatile(
        "mma.sync.aligned.m16n8k16.row.col.f32.bf16.bf16.f32 "
        "{%0,%1,%2,%3}, {%4,%5,%6,%7}, {%8,%9}, {%0,%1,%2,%3};"
        : "+f"(d[0]), "+f"(d[1]), "+f"(d[2]), "+f"(d[3])
        : "r"(a[0]), "r"(a[1]), "r"(a[2]), "r"(a[3]), "r"(b0), "r"(b1));
}

static __device__ __forceinline__ uint32_t pack_bf16x2(float lo, float hi) {
    uint32_t r;
    asm("cvt.rn.bf16x2.f32 %0, %1, %2;" : "=r"(r) : "f"(hi), "f"(lo));
    return r;
}

// ------------------------- small prep kernels ------------------------------
__global__ void k_cvt_x(const float* __restrict__ in) {
    int n = M_ROWS * DIM;
    for (int i = blockIdx.x * blockDim.x + threadIdx.x; i < n;
         i += gridDim.x * blockDim.x)
        g_xb[i] = __float2bfloat16(in[i]);
}
__global__ void k_cvt_wl(const float* __restrict__ in) {
    int n = NPROTO * DIM;
    for (int i = blockIdx.x * blockDim.x + threadIdx.x; i < n;
         i += gridDim.x * blockDim.x)
        g_wl[i] = __float2bfloat16(in[i]);
}
// per-d: fp32 colsum over 4096 prototypes + bf16 convert
__global__ void k_wc_prep(const float* __restrict__ wc) {
    int d = blockIdx.x;
    int t = threadIdx.x;
    float s = 0.0f;
    for (int p = t; p < NPROTO; p += 256) {
        float v = wc[(size_t)d * NPROTO + p];
        s += v;
        g_wc[(size_t)d * NPROTO + p] = __float2bfloat16(v);
    }
    __shared__ float red[8];
    for (int o = 16; o; o >>= 1) s += __shfl_xor_sync(0xFFFFFFFFu, s, o);
    if ((t & 31) == 0) red[t >> 5] = s;
    __syncthreads();
    if (t < 32) {
        float v = (t < 8) ? red[t] : 0.0f;
        for (int o = 4; o; o >>= 1) v += __shfl_xor_sync(0xFFFFFFFFu, v, o);
        if (t == 0) g_cs[d] = v;
    }
}
// Z[r] = sum_p a[r,p]  (deterministic; same bf16 a that GEMM2 consumes)
__global__ void k_rowsum() {
    int row = blockIdx.x;
    const uint4* p = reinterpret_cast<const uint4*>(g_S + (size_t)row * NPROTO);
    float s = 0.0f;
    for (int i = threadIdx.x; i < NPROTO / 8; i += 256) {
        uint4 v = p[i];
        const uint32_t w[4] = {v.x, v.y, v.z, v.w};
#pragma unroll
        for (int q = 0; q < 4; q++) {
            __nv_bfloat162 h = *reinterpret_cast<const __nv_bfloat162*>(&w[q]);
            float2 f = __bfloat1622float2(h);
            s += f.x + f.y;
        }
    }
    __shared__ float red[8];
    int t = threadIdx.x;
    for (int o = 16; o; o >>= 1) s += __shfl_xor_sync(0xFFFFFFFFu, s, o);
    if ((t & 31) == 0) red[t >> 5] = s;
    __syncthreads();
    if (t < 32) {
        float v = (t < 8) ? red[t] : 0.0f;
        for (int o = 4; o; o >>= 1) v += __shfl_xor_sync(0xFFFFFFFFu, v, o);
        if (t == 0) g_Z[row] = v;
    }
}

// ------------------------- main HMMA GEMM ----------------------------------
// MODE 1: A=g_xb [16384,768], B=g_wl [4096,768];  epi: g_S = bf16(expm1(beta*acc))
// MODE 2: A=g_S  [16384,4096], B=g_wc [768,4096]; epi: out = (g_cs + acc)/(4096+Z)
template <int MODE>
__global__ void __launch_bounds__(256, 1) gemm_mma(float* __restrict__ out) {
    const __nv_bfloat16* A;
    const __nv_bfloat16* B;
    int ldA, ldB, nK;
    if constexpr (MODE == 1) {
        A = g_xb; B = g_wl; ldA = DIM; ldB = DIM; nK = DIM / KC;          // 12
    } else {
        A = g_S;  B = g_wc; ldA = NPROTO; ldB = NPROTO; nK = NPROTO / KC; // 64
    }

    extern __shared__ char dsm[];
    const uint32_t base = (smem_u32(dsm) + 1023u) & ~1023u;

    const int tid = threadIdx.x;
    const int l   = tid & 31;
    const int wid = tid >> 5;
    const int wm  = wid >> 2;     // 0..1  (64-row slab)
    const int wn  = wid & 3;      // 0..3  (32-col slab)
    const int m0  = blockIdx.y * TILE_M;
    const int n0  = blockIdx.x * TILE_N;

    auto load_tile = [&](int kk, int st) {
        const uint32_t sA = base + st * STAGE_BYTES;
        const uint32_t sB = sA + STAGE_A;
        const __nv_bfloat16* Ag = A + (size_t)m0 * ldA + kk * KC;
#pragma unroll
        for (int s = 0; s < 4; s++) {
            int slot = tid + s * 256;
            int r = slot >> 3, seg = slot & 7;
            cpasync16(sA + SWZ(r * 128 + seg * 16), Ag + (size_t)r * ldA + seg * 8);
        }
        const __nv_bfloat16* Bg = B + (size_t)n0 * ldB + kk * KC;
#pragma unroll
        for (int s = 0; s < 4; s++) {
            int slot = tid + s * 256;
            int r = slot >> 3, seg = slot & 7;
            cpasync16(sB + SWZ(r * 128 + seg * 16), Bg + (size_t)r * ldB + seg * 8);
        }
        cp_commit();
    };

    float acc[4][4][4];
#pragma unroll
    for (int i = 0; i < 4; i++)
#pragma unroll
        for (int j = 0; j < 4; j++)
#pragma unroll
            for (int q = 0; q < 4; q++) acc[i][j][q] = 0.0f;

    // lane-invariant address components
    const int a_row = wm * 64 + (l & 15);             // + mf*16
    const int a_kb  = (l >> 4) * 16;                  // byte offset in k
    const int b_row = wn * 32 + ((l >> 3) & 1) * 8 + (l & 7);   // + nh*16
    const int b_kb  = (l >> 4) * 16;

    load_tile(0, 0);
    load_tile(1, 1);

    for (int k = 0; k < nK; k++) {
        cp_wait<1>();                 // tile k landed
        __syncthreads();              // everyone done reading stage (k-1)%3
        if (k + 2 < nK) load_tile(k + 2, (k + 2) % STAGES);
        else            cp_commit();  // keep group count consistent

        const uint32_t sA = base + (k % STAGES) * STAGE_BYTES;
        const uint32_t sB = sA + STAGE_A;
#pragma unroll
        for (int ks = 0; ks < 4; ks++) {
            uint32_t af[4][4];
#pragma unroll
            for (int mf = 0; mf < 4; mf++)
                ldsm4(af[mf], sA + SWZ((a_row + mf * 16) * 128 + ks * 32 + a_kb));
            uint32_t bf[2][4];
#pragma unroll
            for (int nh = 0; nh < 2; nh++)
                ldsm4(bf[nh], sB + SWZ((b_row + nh * 16) * 128 + ks * 32 + b_kb));
#pragma unroll
            for (int mf = 0; mf < 4; mf++)
#pragma unroll
                for (int nf = 0; nf < 4; nf++)
                    mma16816(acc[mf][nf], af[mf],
                             bf[nf >> 1][nf & 1], bf[nf >> 1][2 + (nf & 1)]);
        }
    }

    // ------------------------- epilogue -------------------------------------
    const int col0 = n0 + wn * 32 + (l & 3) * 2;      // + nf*8
    const int row0 = m0 + wm * 64 + (l >> 2);         // + mf*16 (+8)

    if constexpr (MODE == 1) {
#pragma unroll
        for (int mf = 0; mf < 4; mf++) {
            int r = row0 + mf * 16;
#pragma unroll
            for (int nf = 0; nf < 4; nf++) {
                int c = col0 + nf * 8;
                float e0 = __expf(acc[mf][nf][0] * BETA_F) - 1.0f;
                float e1 = __expf(acc[mf][nf][1] * BETA_F) - 1.0f;
                float e2 = __expf(acc[mf][nf][2] * BETA_F) - 1.0f;
                float e3 = __expf(acc[mf][nf][3] * BETA_F) - 1.0f;
                uint32_t p01 = pack_bf16x2(e0, e1);
                uint32_t p23 = pack_bf16x2(e2, e3);
                *reinterpret_cast<uint32_t*>(g_S + (size_t)r * NPROTO + c) = p01;
                *reinterpret_cast<uint32_t*>(g_S + (size_t)(r + 8) * NPROTO + c) = p23;
            }
        }
    } else {
        float cs0[4], cs1[4];
#pragma unroll
        for (int nf = 0; nf < 4; nf++) {
            cs0[nf] = __ldg(&g_cs[col0 + nf * 8]);
            cs1[nf] = __ldg(&g_cs[col0 + nf * 8 + 1]);
        }
#pragma unroll
        for (int mf = 0; mf < 4; mf++) {
            int r = row0 + mf * 16;
            float iz0 = 1.0f / (4096.0f + __ldg(&g_Z[r]));
            float iz1 = 1.0f / (4096.0f + __ldg(&g_Z[r + 8]));
#pragma unroll
            for (int nf = 0; nf < 4; nf++) {
                int c = col0 + nf * 8;
                float2 v0, v1;
                v0.x = (cs0[nf] + acc[mf][nf][0]) * iz0;
                v0.y = (cs1[nf] + acc[mf][nf][1]) * iz0;
                v1.x = (cs0[nf] + acc[mf][nf][2]) * iz1;
                v1.y = (cs1[nf] + acc[mf][nf][3]) * iz1;
                *reinterpret_cast<float2*>(out + (size_t)r * DIM + c) = v0;
                *reinterpret_cast<float2*>(out + (size_t)(r + 8) * DIM + c) = v1;
            }
        }
    }
}

// ------------------------- launch ------------------------------------------
extern "C" void kernel_launch(void* const* d_in, const int* in_sizes, int n_in,
                              void* d_out, int out_size) {
    (void)in_sizes; (void)n_in; (void)out_size;
    const float* x  = (const float*)d_in[0];
    const float* wl = (const float*)d_in[1];
    const float* wc = (const float*)d_in[2];
    float* out = (float*)d_out;

    cudaFuncSetAttribute(gemm_mma<1>, cudaFuncAttributeMaxDynamicSharedMemorySize,
                         SMEM_DYN);
    cudaFuncSetAttribute(gemm_mma<2>, cudaFuncAttributeMaxDynamicSharedMemorySize,
                         SMEM_DYN);

    k_cvt_x <<<2048, 256>>>(x);
    k_cvt_wl<<<1024, 256>>>(wl);
    k_wc_prep<<<DIM, 256>>>(wc);

    dim3 g1(NPROTO / TILE_N, M_ROWS / TILE_M);   // (32, 128)
    gemm_mma<1><<<g1, 256, SMEM_DYN>>>(nullptr);

    k_rowsum<<<M_ROWS, 256>>>();

    dim3 g2(DIM / TILE_N, M_ROWS / TILE_M);      // (6, 128)
    gemm_mma<2><<<g2, 256, SMEM_DYN>>>(out);
}

// round 3
// speedup vs baseline: 1.1471x; 1.1471x over previous
#include <cuda_runtime.h>
#include <cuda_bf16.h>
#include <cstdint>

// ---------------------------------------------------------------------------
// HopfieldLayer: content = softmax(x @ wl^T * beta) @ wc^T
//   x [16384,768] f32, wl [4096,768] f32, wc [768,4096] f32 -> out [16384,768] f32
// Decomposed for bf16 precision:
//   a = expm1(beta * (x @ wl^T))                 (GEMM1, bf16 in, fp32 acc)
//   Z[r] = 4096 + sum_p a[r,p]                   (rowsum kernel)
//   out[r,d] = (colsumW[d] + (a @ wc^T)[r,d]) / Z[r]    (GEMM2)
// Engine: mma.sync m16n8k16 bf16 + cp.async 3-stage pipeline + ldmatrix with
// fragment double-buffering (LDSM(ks+1) overlaps MMA(ks)).
// ---------------------------------------------------------------------------

#define M_ROWS 16384
#define NPROTO 4096
#define DIM    768
#define BETA_F 0.03608439182435161f

#define TILE_M 128
#define TILE_N 128
#define KC     64          // bf16 K elements per stage (128 B per smem row)

#define STAGES       3
#define STAGE_A      (TILE_M * 128)          // 16 KB
#define STAGE_B      (TILE_N * 128)          // 16 KB
#define STAGE_BYTES  (STAGE_A + STAGE_B)     // 32 KB
#define SMEM_DYN     (STAGES * STAGE_BYTES + 1024)

// ------------------------- scratch (device globals, no allocs) -------------
__device__ __align__(256) __nv_bfloat16 g_xb[(size_t)M_ROWS * DIM];
__device__ __align__(256) __nv_bfloat16 g_wl[(size_t)NPROTO * DIM];
__device__ __align__(256) __nv_bfloat16 g_wc[(size_t)DIM * NPROTO];
__device__ __align__(256) __nv_bfloat16 g_S [(size_t)M_ROWS * NPROTO];
__device__ float g_Z[M_ROWS];
__device__ float g_cs[DIM];

// ------------------------- PTX helpers -------------------------------------
static __device__ __forceinline__ uint32_t smem_u32(const void* p) {
    uint32_t a;
    asm("{ .reg .u64 t; cvta.to.shared.u64 t, %1; cvt.u32.u64 %0, t; }"
        : "=r"(a) : "l"(p));
    return a;
}

#define SWZ(o) ((o) ^ (((o) >> 3) & 0x70))

static __device__ __forceinline__ void cpasync16(uint32_t dst, const void* src) {
    asm volatile("cp.async.cg.shared.global [%0], [%1], 16;"
                 :: "r"(dst), "l"(src));
}
static __device__ __forceinline__ void cp_commit() {
    asm volatile("cp.async.commit_group;");
}
template <int N>
static __device__ __forceinline__ void cp_wait() {
    asm volatile("cp.async.wait_group %0;" :: "n"(N));
}

static __device__ __forceinline__ void ldsm4(uint32_t* r, uint32_t addr) {
    asm volatile("ldmatrix.sync.aligned.m8n8.x4.shared.b16 {%0,%1,%2,%3}, [%4];"
                 : "=r"(r[0]), "=r"(r[1]), "=r"(r[2]), "=r"(r[3])
                 : "r"(addr));
}

static __device__ __forceinline__ void mma16816(float* d, const uint32_t* a,
                                                uint32_t b0, uint32_t b1) {
    asm volatile(
        "mma.sync.aligned.m16n8k16.row.col.f32.bf16.bf16.f32 "
        "{%0,%1,%2,%3}, {%4,%5,%6,%7}, {%8,%9}, {%0,%1,%2,%3};"
        : "+f"(d[0]), "+f"(d[1]), "+f"(d[2]), "+f"(d[3])
        : "r"(a[0]), "r"(a[1]), "r"(a[2]), "r"(a[3]), "r"(b0), "r"(b1));
}

static __device__ __forceinline__ uint32_t pack_bf16x2(float lo, float hi) {
    uint32_t r;
    asm("cvt.rn.bf16x2.f32 %0, %1, %2;" : "=r"(r) : "f"(hi), "f"(lo));
    return r;
}

// ------------------------- small prep kernels ------------------------------
__global__ void k_cvt_x(const float* __restrict__ in) {
    int n = M_ROWS * DIM;
    for (int i = blockIdx.x * blockDim.x + threadIdx.x; i < n;
         i += gridDim.x * blockDim.x)
        g_xb[i] = __float2bfloat16(in[i]);
}
__global__ void k_cvt_wl(const float* __restrict__ in) {
    int n = NPROTO * DIM;
    for (int i = blockIdx.x * blockDim.x + threadIdx.x; i < n;
         i += gridDim.x * blockDim.x)
        g_wl[i] = __float2bfloat16(in[i]);
}
// per-d: fp32 colsum over 4096 prototypes + bf16 convert
__global__ void k_wc_prep(const float* __restrict__ wc) {
    int d = blockIdx.x;
    int t = threadIdx.x;
    float s = 0.0f;
    for (int p = t; p < NPROTO; p += 256) {
        float v = wc[(size_t)d * NPROTO + p];
        s += v;
        g_wc[(size_t)d * NPROTO + p] = __float2bfloat16(v);
    }
    __shared__ float red[8];
    for (int o = 16; o; o >>= 1) s += __shfl_xor_sync(0xFFFFFFFFu, s, o);
    if ((t & 31) == 0) red[t >> 5] = s;
    __syncthreads();
    if (t < 32) {
        float v = (t < 8) ? red[t] : 0.0f;
        for (int o = 4; o; o >>= 1) v += __shfl_xor_sync(0xFFFFFFFFu, v, o);
        if (t == 0) g_cs[d] = v;
    }
}
// Z[r] = sum_p a[r,p]  (deterministic; same bf16 a that GEMM2 consumes)
__global__ void k_rowsum() {
    int row = blockIdx.x;
    const uint4* p = reinterpret_cast<const uint4*>(g_S + (size_t)row * NPROTO);
    float s = 0.0f;
    for (int i = threadIdx.x; i < NPROTO / 8; i += 256) {
        uint4 v = p[i];
        const uint32_t w[4] = {v.x, v.y, v.z, v.w};
#pragma unroll
        for (int q = 0; q < 4; q++) {
            __nv_bfloat162 h = *reinterpret_cast<const __nv_bfloat162*>(&w[q]);
            float2 f = __bfloat1622float2(h);
            s += f.x + f.y;
        }
    }
    __shared__ float red[8];
    int t = threadIdx.x;
    for (int o = 16; o; o >>= 1) s += __shfl_xor_sync(0xFFFFFFFFu, s, o);
    if ((t & 31) == 0) red[t >> 5] = s;
    __syncthreads();
    if (t < 32) {
        float v = (t < 8) ? red[t] : 0.0f;
        for (int o = 4; o; o >>= 1) v += __shfl_xor_sync(0xFFFFFFFFu, v, o);
        if (t == 0) g_Z[row] = v;
    }
}

// ------------------------- main HMMA GEMM ----------------------------------
// MODE 1: A=g_xb [16384,768], B=g_wl [4096,768];  epi: g_S = bf16(expm1(beta*acc))
// MODE 2: A=g_S  [16384,4096], B=g_wc [768,4096]; epi: out = (g_cs + acc)/(4096+Z)
template <int MODE>
__global__ void __launch_bounds__(256, 1) gemm_mma(float* __restrict__ out) {
    const __nv_bfloat16* A;
    const __nv_bfloat16* B;
    int ldA, ldB, nK;
    if constexpr (MODE == 1) {
        A = g_xb; B = g_wl; ldA = DIM; ldB = DIM; nK = DIM / KC;          // 12
    } else {
        A = g_S;  B = g_wc; ldA = NPROTO; ldB = NPROTO; nK = NPROTO / KC; // 64
    }

    extern __shared__ char dsm[];
    const uint32_t base = (smem_u32(dsm) + 1023u) & ~1023u;

    const int tid = threadIdx.x;
    const int l   = tid & 31;
    const int wid = tid >> 5;
    const int wm  = wid >> 2;     // 0..1  (64-row slab)
    const int wn  = wid & 3;      // 0..3  (32-col slab)
    const int m0  = blockIdx.y * TILE_M;
    const int n0  = blockIdx.x * TILE_N;

    // ---- cp.async source pointers / dest offsets (precomputed per thread)
    const int ld_r   = tid >> 3;          // 0..31  (row step 32)
    const int ld_seg = tid & 7;           // 16B segment in 128B row
    const __nv_bfloat16* Ag = A + (size_t)(m0 + ld_r) * ldA + ld_seg * 8;
    const __nv_bfloat16* Bg = B + (size_t)(n0 + ld_r) * ldB + ld_seg * 8;
    uint32_t dA[4], dB[4];
#pragma unroll
    for (int s = 0; s < 4; s++) {
        dA[s] = SWZ((ld_r + s * 32) * 128 + ld_seg * 16);
        dB[s] = STAGE_A + SWZ((ld_r + s * 32) * 128 + ld_seg * 16);
    }

    auto load_tile = [&](int kk, int st) {
        const uint32_t sS = base + st * STAGE_BYTES;
        const __nv_bfloat16* a = Ag + kk * KC;
        const __nv_bfloat16* b = Bg + kk * KC;
#pragma unroll
        for (int s = 0; s < 4; s++)
            cpasync16(sS + dA[s], a + (size_t)(s * 32) * ldA);
#pragma unroll
        for (int s = 0; s < 4; s++)
            cpasync16(sS + dB[s], b + (size_t)(s * 32) * ldB);
        cp_commit();
    };

    float acc[4][4][4];
#pragma unroll
    for (int i = 0; i < 4; i++)
#pragma unroll
        for (int j = 0; j < 4; j++)
#pragma unroll
            for (int q = 0; q < 4; q++) acc[i][j][q] = 0.0f;

    // ---- ldmatrix addressing: SWZ(row*128 + d) = row*128 + (d ^ ((row&7)<<4))
    const int a_row = wm * 64 + (l & 15);                       // + mf*16
    const int b_row = wn * 32 + ((l >> 3) & 1) * 8 + (l & 7);   // + nh*16
    const int kb    = (l >> 4) * 16;                            // 16B k-half
    const uint32_t Ta = (uint32_t)((a_row & 7) << 4);
    const uint32_t Tb = (uint32_t)((b_row & 7) << 4);
    uint32_t aoff[4], boff[2];
#pragma unroll
    for (int mf = 0; mf < 4; mf++) aoff[mf] = (a_row + mf * 16) * 128;
#pragma unroll
    for (int nh = 0; nh < 2; nh++) boff[nh] = STAGE_A + (b_row + nh * 16) * 128;
    uint32_t dka[4], dkb[4];
#pragma unroll
    for (int ks = 0; ks < 4; ks++) {
        dka[ks] = (uint32_t)(kb + ks * 32) ^ Ta;
        dkb[ks] = (uint32_t)(kb + ks * 32) ^ Tb;
    }

    load_tile(0, 0);
    load_tile(1, 1);

    uint32_t af[2][4][4];
    uint32_t bf[2][2][4];

    for (int k = 0; k < nK; k++) {
        cp_wait<1>();                 // tile k landed
        __syncthreads();              // all warps done with stage (k+2)%3 regs
        if (k + 2 < nK) load_tile(k + 2, (k + 2) % STAGES);
        else            cp_commit();  // keep group accounting consistent

        const uint32_t sS = base + (k % STAGES) * STAGE_BYTES;

        // prefetch ks=0 fragments
#pragma unroll
        for (int mf = 0; mf < 4; mf++) ldsm4(af[0][mf], sS + aoff[mf] + dka[0]);
#pragma unroll
        for (int nh = 0; nh < 2; nh++) ldsm4(bf[0][nh], sS + boff[nh] + dkb[0]);

#pragma unroll
        for (int ks = 0; ks < 4; ks++) {
            const int cur = ks & 1, nxt = cur ^ 1;
            if (ks < 3) {
#pragma unroll
                for (int mf = 0; mf < 4; mf++)
                    ldsm4(af[nxt][mf], sS + aoff[mf] + dka[ks + 1]);
#pragma unroll
                for (int nh = 0; nh < 2; nh++)
                    ldsm4(bf[nxt][nh], sS + boff[nh] + dkb[ks + 1]);
            }
#pragma unroll
            for (int mf = 0; mf < 4; mf++)
#pragma unroll
                for (int nf = 0; nf < 4; nf++)
                    mma16816(acc[mf][nf], af[cur][mf],
                             bf[cur][nf >> 1][nf & 1],
                             bf[cur][nf >> 1][2 + (nf & 1)]);
        }
    }

    // ------------------------- epilogue -------------------------------------
    const int col0 = n0 + wn * 32 + (l & 3) * 2;      // + nf*8
    const int row0 = m0 + wm * 64 + (l >> 2);         // + mf*16 (+8)

    if constexpr (MODE == 1) {
#pragma unroll
        for (int mf = 0; mf < 4; mf++) {
            int r = row0 + mf * 16;
#pragma unroll
            for (int nf = 0; nf < 4; nf++) {
                int c = col0 + nf * 8;
                float e0 = __expf(acc[mf][nf][0] * BETA_F) - 1.0f;
                float e1 = __expf(acc[mf][nf][1] * BETA_F) - 1.0f;
                float e2 = __expf(acc[mf][nf][2] * BETA_F) - 1.0f;
                float e3 = __expf(acc[mf][nf][3] * BETA_F) - 1.0f;
                uint32_t p01 = pack_bf16x2(e0, e1);
                uint32_t p23 = pack_bf16x2(e2, e3);
                *reinterpret_cast<uint32_t*>(g_S + (size_t)r * NPROTO + c) = p01;
                *reinterpret_cast<uint32_t*>(g_S + (size_t)(r + 8) * NPROTO + c) = p23;
            }
        }
    } else {
        float cs0[4], cs1[4];
#pragma unroll
        for (int nf = 0; nf < 4; nf++) {
            cs0[nf] = __ldg(&g_cs[col0 + nf * 8]);
            cs1[nf] = __ldg(&g_cs[col0 + nf * 8 + 1]);
        }
#pragma unroll
        for (int mf = 0; mf < 4; mf++) {
            int r = row0 + mf * 16;
            float iz0 = 1.0f / (4096.0f + __ldg(&g_Z[r]));
            float iz1 = 1.0f / (4096.0f + __ldg(&g_Z[r + 8]));
#pragma unroll
            for (int nf = 0; nf < 4; nf++) {
                int c = col0 + nf * 8;
                float2 v0, v1;
                v0.x = (cs0[nf] + acc[mf][nf][0]) * iz0;
                v0.y = (cs1[nf] + acc[mf][nf][1]) * iz0;
                v1.x = (cs0[nf] + acc[mf][nf][2]) * iz1;
                v1.y = (cs1[nf] + acc[mf][nf][3]) * iz1;
                *reinterpret_cast<float2*>(out + (size_t)r * DIM + c) = v0;
                *reinterpret_cast<float2*>(out + (size_t)(r + 8) * DIM + c) = v1;
            }
        }
    }
}

// ------------------------- launch ------------------------------------------
extern "C" void kernel_launch(void* const* d_in, const int* in_sizes, int n_in,
                              void* d_out, int out_size) {
    (void)in_sizes; (void)n_in; (void)out_size;
    const float* x  = (const float*)d_in[0];
    const float* wl = (const float*)d_in[1];
    const float* wc = (const float*)d_in[2];
    float* out = (float*)d_out;

    cudaFuncSetAttribute(gemm_mma<1>, cudaFuncAttributeMaxDynamicSharedMemorySize,
                         SMEM_DYN);
    cudaFuncSetAttribute(gemm_mma<2>, cudaFuncAttributeMaxDynamicSharedMemorySize,
                         SMEM_DYN);

    k_cvt_x <<<2048, 256>>>(x);
    k_cvt_wl<<<1024, 256>>>(wl);
    k_wc_prep<<<DIM, 256>>>(wc);

    dim3 g1(NPROTO / TILE_N, M_ROWS / TILE_M);   // (32, 128)
    gemm_mma<1><<<g1, 256, SMEM_DYN>>>(nullptr);

    k_rowsum<<<M_ROWS, 256>>>();

    dim3 g2(DIM / TILE_N, M_ROWS / TILE_M);      // (6, 128)
    gemm_mma<2><<<g2, 256, SMEM_DYN>>>(out);
}

// round 4
// speedup vs baseline: 1.1744x; 1.0238x over previous
#include <cuda_runtime.h>
#include <cuda_bf16.h>
#include <cstdint>

// ---------------------------------------------------------------------------
// HopfieldLayer: content = softmax(x @ wl^T * beta) @ wc^T
// Decomposed for bf16 precision:
//   a = expm1(beta * (x @ wl^T))                 (GEMM1, fused partial row-sums)
//   Z[r] = 4096 + sum_p a[r,p]                   (tiny reduce of GEMM1 partials)
//   out[r,d] = (colsumW[d] + (a @ wc^T)[r,d]) / Z[r]    (GEMM2)
// Engine: mma.sync m16n8k16 bf16, cp.async 3-stage pipeline, ldmatrix with
// fragment double-buffering. 128x256 CTA tile, 64x64 warp tile (MMA:LDSM=2:1).
// ---------------------------------------------------------------------------

#define M_ROWS 16384
#define NPROTO 4096
#define DIM    768
#define BETA_F 0.03608439182435161f

#define TILE_M 128
#define TILE_N 256
#define KC     64          // bf16 K elements per stage (128 B per smem row)

#define STAGES       3
#define STAGE_A      (TILE_M * 128)          // 16 KB
#define STAGE_B      (TILE_N * 128)          // 32 KB
#define STAGE_BYTES  (STAGE_A + STAGE_B)     // 48 KB
#define SMEM_DYN     (STAGES * STAGE_BYTES + 1024)

#define ZCHUNKS 64   // (NPROTO/TILE_N)=16 col-tiles x 4 warp n-slabs

// ------------------------- scratch (device globals, no allocs) -------------
__device__ __align__(256) __nv_bfloat16 g_xb[(size_t)M_ROWS * DIM];
__device__ __align__(256) __nv_bfloat16 g_wl[(size_t)NPROTO * DIM];
__device__ __align__(256) __nv_bfloat16 g_wc[(size_t)DIM * NPROTO];
__device__ __align__(256) __nv_bfloat16 g_S [(size_t)M_ROWS * NPROTO];
__device__ float g_Zp[(size_t)ZCHUNKS * M_ROWS];
__device__ float g_Z[M_ROWS];
__device__ float g_cs[DIM];

// ------------------------- PTX helpers -------------------------------------
static __device__ __forceinline__ uint32_t smem_u32(const void* p) {
    uint32_t a;
    asm("{ .reg .u64 t; cvta.to.shared.u64 t, %1; cvt.u32.u64 %0, t; }"
        : "=r"(a) : "l"(p));
    return a;
}

#define SWZ(o) ((o) ^ (((o) >> 3) & 0x70))

static __device__ __forceinline__ void cpasync16(uint32_t dst, const void* src) {
    asm volatile("cp.async.cg.shared.global [%0], [%1], 16;"
                 :: "r"(dst), "l"(src));
}
static __device__ __forceinline__ void cp_commit() {
    asm volatile("cp.async.commit_group;");
}
template <int N>
static __device__ __forceinline__ void cp_wait() {
    asm volatile("cp.async.wait_group %0;" :: "n"(N));
}

static __device__ __forceinline__ void ldsm4(uint32_t* r, uint32_t addr) {
    asm volatile("ldmatrix.sync.aligned.m8n8.x4.shared.b16 {%0,%1,%2,%3}, [%4];"
                 : "=r"(r[0]), "=r"(r[1]), "=r"(r[2]), "=r"(r[3])
                 : "r"(addr));
}

static __device__ __forceinline__ void mma16816(float* d, const uint32_t* a,
                                                uint32_t b0, uint32_t b1) {
    asm volatile(
        "mma.sync.aligned.m16n8k16.row.col.f32.bf16.bf16.f32 "
        "{%0,%1,%2,%3}, {%4,%5,%6,%7}, {%8,%9}, {%0,%1,%2,%3};"
        : "+f"(d[0]), "+f"(d[1]), "+f"(d[2]), "+f"(d[3])
        : "r"(a[0]), "r"(a[1]), "r"(a[2]), "r"(a[3]), "r"(b0), "r"(b1));
}

static __device__ __forceinline__ uint32_t pack_bf16x2(float lo, float hi) {
    uint32_t r;
    asm("cvt.rn.bf16x2.f32 %0, %1, %2;" : "=r"(r) : "f"(hi), "f"(lo));
    return r;
}

// ------------------------- small prep kernels ------------------------------
__global__ void k_cvt_x(const float* __restrict__ in) {
    int n = M_ROWS * DIM / 4;
    const float4* p = reinterpret_cast<const float4*>(in);
    uint2* q = reinterpret_cast<uint2*>(g_xb);
    for (int i = blockIdx.x * blockDim.x + threadIdx.x; i < n;
         i += gridDim.x * blockDim.x) {
        float4 v = p[i];
        uint2 o;
        o.x = pack_bf16x2(v.x, v.y);
        o.y = pack_bf16x2(v.z, v.w);
        q[i] = o;
    }
}
__global__ void k_cvt_wl(const float* __restrict__ in) {
    int n = NPROTO * DIM / 4;
    const float4* p = reinterpret_cast<const float4*>(in);
    uint2* q = reinterpret_cast<uint2*>(g_wl);
    for (int i = blockIdx.x * blockDim.x + threadIdx.x; i < n;
         i += gridDim.x * blockDim.x) {
        float4 v = p[i];
        uint2 o;
        o.x = pack_bf16x2(v.x, v.y);
        o.y = pack_bf16x2(v.z, v.w);
        q[i] = o;
    }
}
// per-d: fp32 colsum over 4096 prototypes + bf16 convert
__global__ void k_wc_prep(const float* __restrict__ wc) {
    int d = blockIdx.x;
    int t = threadIdx.x;
    float s = 0.0f;
    const float4* src = reinterpret_cast<const float4*>(wc + (size_t)d * NPROTO);
    uint2* dst = reinterpret_cast<uint2*>(g_wc + (size_t)d * NPROTO);
    for (int i = t; i < NPROTO / 4; i += 256) {
        float4 v = src[i];
        s += (v.x + v.y) + (v.z + v.w);
        uint2 o;
        o.x = pack_bf16x2(v.x, v.y);
        o.y = pack_bf16x2(v.z, v.w);
        dst[i] = o;
    }
    __shared__ float red[8];
    for (int o = 16; o; o >>= 1) s += __shfl_xor_sync(0xFFFFFFFFu, s, o);
    if ((t & 31) == 0) red[t >> 5] = s;
    __syncthreads();
    if (t < 32) {
        float v = (t < 8) ? red[t] : 0.0f;
        for (int o = 4; o; o >>= 1) v += __shfl_xor_sync(0xFFFFFFFFu, v, o);
        if (t == 0) g_cs[d] = v;
    }
}
// Z[r] = sum over ZCHUNKS partials (deterministic fixed order)
__global__ void k_zreduce() {
    int r = blockIdx.x * blockDim.x + threadIdx.x;
    float s = 0.0f;
#pragma unroll 8
    for (int c = 0; c < ZCHUNKS; c++) s += g_Zp[(size_t)c * M_ROWS + r];
    g_Z[r] = s;
}

// ------------------------- main HMMA GEMM ----------------------------------
// MODE 1: A=g_xb [16384,768], B=g_wl [4096,768];
//         epi: g_S = bf16(expm1(beta*acc)), partial row sums -> g_Zp
// MODE 2: A=g_S [16384,4096], B=g_wc [768,4096];
//         epi: out = (g_cs + acc)/(4096+Z)
template <int MODE>
__global__ void __launch_bounds__(256, 1) gemm_mma(float* __restrict__ out) {
    const __nv_bfloat16* A;
    const __nv_bfloat16* B;
    int ldA, ldB, nK;
    if constexpr (MODE == 1) {
        A = g_xb; B = g_wl; ldA = DIM; ldB = DIM; nK = DIM / KC;          // 12
    } else {
        A = g_S;  B = g_wc; ldA = NPROTO; ldB = NPROTO; nK = NPROTO / KC; // 64
    }

    extern __shared__ char dsm[];
    const uint32_t base = (smem_u32(dsm) + 1023u) & ~1023u;

    const int tid = threadIdx.x;
    const int l   = tid & 31;
    const int wid = tid >> 5;
    const int wm  = wid >> 2;     // 0..1  (64-row slab)
    const int wn  = wid & 3;      // 0..3  (64-col slab)
    const int m0  = blockIdx.y * TILE_M;
    const int n0  = blockIdx.x * TILE_N;

    // ---- cp.async source pointers / dest offsets
    const int ld_r   = tid >> 3;          // 0..31
    const int ld_seg = tid & 7;           // 16B segment in 128B row
    const __nv_bfloat16* Ag = A + (size_t)(m0 + ld_r) * ldA + ld_seg * 8;
    const __nv_bfloat16* Bg = B + (size_t)(n0 + ld_r) * ldB + ld_seg * 8;
    uint32_t dA[4], dB[8];
#pragma unroll
    for (int s = 0; s < 4; s++)
        dA[s] = SWZ((ld_r + s * 32) * 128 + ld_seg * 16);
#pragma unroll
    for (int s = 0; s < 8; s++)
        dB[s] = STAGE_A + SWZ((ld_r + s * 32) * 128 + ld_seg * 16);

    auto load_tile = [&](int kk, int st) {
        const uint32_t sS = base + st * STAGE_BYTES;
        const __nv_bfloat16* a = Ag + kk * KC;
        const __nv_bfloat16* b = Bg + kk * KC;
#pragma unroll
        for (int s = 0; s < 4; s++)
            cpasync16(sS + dA[s], a + (size_t)(s * 32) * ldA);
#pragma unroll
        for (int s = 0; s < 8; s++)
            cpasync16(sS + dB[s], b + (size_t)(s * 32) * ldB);
        cp_commit();
    };

    float acc[4][8][4];
#pragma unroll
    for (int i = 0; i < 4; i++)
#pragma unroll
        for (int j = 0; j < 8; j++)
#pragma unroll
            for (int q = 0; q < 4; q++) acc[i][j][q] = 0.0f;

    // ---- ldmatrix addressing: SWZ(row*128 + d) = row*128 + (d ^ ((row&7)<<4))
    const int a_row = wm * 64 + (l & 15);                       // + mf*16
    const int b_row = wn * 64 + ((l >> 3) & 1) * 8 + (l & 7);   // + nh*16
    const int kb    = (l >> 4) * 16;                            // 16B k-half
    const uint32_t Ta = (uint32_t)((a_row & 7) << 4);
    const uint32_t Tb = (uint32_t)((b_row & 7) << 4);
    uint32_t aoff[4], boff[4];
#pragma unroll
    for (int mf = 0; mf < 4; mf++) aoff[mf] = (a_row + mf * 16) * 128;
#pragma unroll
    for (int nh = 0; nh < 4; nh++) boff[nh] = STAGE_A + (b_row + nh * 16) * 128;
    uint32_t dka[4], dkb[4];
#pragma unroll
    for (int ks = 0; ks < 4; ks++) {
        dka[ks] = (uint32_t)(kb + ks * 32) ^ Ta;
        dkb[ks] = (uint32_t)(kb + ks * 32) ^ Tb;
    }

    load_tile(0, 0);
    load_tile(1, 1);

    uint32_t af[2][4][4];
    uint32_t bf[2][4][4];

    for (int k = 0; k < nK; k++) {
        cp_wait<1>();                 // tile k landed
        __syncthreads();              // all warps done with stage (k+2)%3
        if (k + 2 < nK) load_tile(k + 2, (k + 2) % STAGES);
        else            cp_commit();  // keep group accounting consistent

        const uint32_t sS = base + (k % STAGES) * STAGE_BYTES;

        // prefetch ks=0 fragments
#pragma unroll
        for (int mf = 0; mf < 4; mf++) ldsm4(af[0][mf], sS + aoff[mf] + dka[0]);
#pragma unroll
        for (int nh = 0; nh < 4; nh++) ldsm4(bf[0][nh], sS + boff[nh] + dkb[0]);

#pragma unroll
        for (int ks = 0; ks < 4; ks++) {
            const int cur = ks & 1, nxt = cur ^ 1;
            if (ks < 3) {
#pragma unroll
                for (int mf = 0; mf < 4; mf++)
                    ldsm4(af[nxt][mf], sS + aoff[mf] + dka[ks + 1]);
#pragma unroll
                for (int nh = 0; nh < 4; nh++)
                    ldsm4(bf[nxt][nh], sS + boff[nh] + dkb[ks + 1]);
            }
#pragma unroll
            for (int mf = 0; mf < 4; mf++)
#pragma unroll
                for (int nf = 0; nf < 8; nf++)
                    mma16816(acc[mf][nf], af[cur][mf],
                             bf[cur][nf >> 1][nf & 1],
                             bf[cur][nf >> 1][2 + (nf & 1)]);
        }
    }

    // ------------------------- epilogue -------------------------------------
    const int col0 = n0 + wn * 64 + (l & 3) * 2;      // + nf*8
    const int row0 = m0 + wm * 64 + (l >> 2);         // + mf*16 (+8)

    if constexpr (MODE == 1) {
        const int zc = blockIdx.x * 4 + wn;           // 0..63
#pragma unroll
        for (int mf = 0; mf < 4; mf++) {
            int r = row0 + mf * 16;
            float slo = 0.0f, shi = 0.0f;
#pragma unroll
            for (int nf = 0; nf < 8; nf++) {
                int c = col0 + nf * 8;
                float e0 = __expf(acc[mf][nf][0] * BETA_F) - 1.0f;
                float e1 = __expf(acc[mf][nf][1] * BETA_F) - 1.0f;
                float e2 = __expf(acc[mf][nf][2] * BETA_F) - 1.0f;
                float e3 = __expf(acc[mf][nf][3] * BETA_F) - 1.0f;
                slo += e0 + e1;
                shi += e2 + e3;
                uint32_t p01 = pack_bf16x2(e0, e1);
                uint32_t p23 = pack_bf16x2(e2, e3);
                *reinterpret_cast<uint32_t*>(g_S + (size_t)r * NPROTO + c) = p01;
                *reinterpret_cast<uint32_t*>(g_S + (size_t)(r + 8) * NPROTO + c) = p23;
            }
            // reduce 64-col partial over the 4 lanes sharing this row (l&3)
            slo += __shfl_xor_sync(0xFFFFFFFFu, slo, 1);
            slo += __shfl_xor_sync(0xFFFFFFFFu, slo, 2);
            shi += __shfl_xor_sync(0xFFFFFFFFu, shi, 1);
            shi += __shfl_xor_sync(0xFFFFFFFFu, shi, 2);
            if ((l & 3) == 0) {
                g_Zp[(size_t)zc * M_ROWS + r]     = slo;
                g_Zp[(size_t)zc * M_ROWS + r + 8] = shi;
            }
        }
    } else {
        float cs0[8], cs1[8];
#pragma unroll
        for (int nf = 0; nf < 8; nf++) {
            cs0[nf] = __ldg(&g_cs[col0 + nf * 8]);
            cs1[nf] = __ldg(&g_cs[col0 + nf * 8 + 1]);
        }
#pragma unroll
        for (int mf = 0; mf < 4; mf++) {
            int r = row0 + mf * 16;
            float iz0 = 1.0f / (4096.0f + __ldg(&g_Z[r]));
            float iz1 = 1.0f / (4096.0f + __ldg(&g_Z[r + 8]));
#pragma unroll
            for (int nf = 0; nf < 8; nf++) {
                int c = col0 + nf * 8;
                float2 v0, v1;
                v0.x = (cs0[nf] + acc[mf][nf][0]) * iz0;
                v0.y = (cs1[nf] + acc[mf][nf][1]) * iz0;
                v1.x = (cs0[nf] + acc[mf][nf][2]) * iz1;
                v1.y = (cs1[nf] + acc[mf][nf][3]) * iz1;
                *reinterpret_cast<float2*>(out + (size_t)r * DIM + c) = v0;
                *reinterpret_cast<float2*>(out + (size_t)(r + 8) * DIM + c) = v1;
            }
        }
    }
}

// ------------------------- launch ------------------------------------------
extern "C" void kernel_launch(void* const* d_in, const int* in_sizes, int n_in,
                              void* d_out, int out_size) {
    (void)in_sizes; (void)n_in; (void)out_size;
    const float* x  = (const float*)d_in[0];
    const float* wl = (const float*)d_in[1];
    const float* wc = (const float*)d_in[2];
    float* out = (float*)d_out;

    cudaFuncSetAttribute(gemm_mma<1>, cudaFuncAttributeMaxDynamicSharedMemorySize,
                         SMEM_DYN);
    cudaFuncSetAttribute(gemm_mma<2>, cudaFuncAttributeMaxDynamicSharedMemorySize,
                         SMEM_DYN);

    k_cvt_x <<<2048, 256>>>(x);
    k_cvt_wl<<<1024, 256>>>(wl);
    k_wc_prep<<<DIM, 256>>>(wc);

    dim3 g1(NPROTO / TILE_N, M_ROWS / TILE_M);   // (16, 128)
    gemm_mma<1><<<g1, 256, SMEM_DYN>>>(nullptr);

    k_zreduce<<<M_ROWS / 256, 256>>>();

    dim3 g2(DIM / TILE_N, M_ROWS / TILE_M);      // (3, 128)
    gemm_mma<2><<<g2, 256, SMEM_DYN>>>(out);
}

// round 5
// speedup vs baseline: 1.2376x; 1.0539x over previous
#include <cuda_runtime.h>
#include <cuda_bf16.h>
#include <cstdint>

// ---------------------------------------------------------------------------
// HopfieldLayer: content = softmax(x @ wl^T * beta) @ wc^T
// Decomposed for bf16 precision:
//   a = expm1(beta * (x @ wl^T))                 (GEMM1, fused partial row-sums)
//   Z[r] = 4096 + sum_p a[r,p]                   (tiny reduce of GEMM1 partials)
//   out[r,d] = (colsumW[d] + (a @ wc^T)[r,d]) / Z[r]    (GEMM2)
// Engine: mma.sync m16n8k16 bf16; cp.async 3-stage ring with mbarrier
// producer/consumer pacing (no per-stage __syncthreads lockstep);
// 128x128 CTA tile, 64x32 warp tile, 2 CTAs/SM.
// ---------------------------------------------------------------------------

#define M_ROWS 16384
#define NPROTO 4096
#define DIM    768
#define BETA_F 0.03608439182435161f

#define TILE_M 128
#define TILE_N 128
#define KC     64          // bf16 K elements per stage (128 B per smem row)

#define STAGES       3
#define STAGE_A      (TILE_M * 128)          // 16 KB
#define STAGE_B      (TILE_N * 128)          // 16 KB
#define STAGE_BYTES  (STAGE_A + STAGE_B)     // 32 KB
#define SMEM_DYN     (STAGES * STAGE_BYTES + 1024)

#define ZCHUNKS 128   // (NPROTO/TILE_N)=32 col-tiles x 4 warp n-slabs

// ------------------------- scratch (device globals, no allocs) -------------
__device__ __align__(256) __nv_bfloat16 g_xb[(size_t)M_ROWS * DIM];
__device__ __align__(256) __nv_bfloat16 g_wl[(size_t)NPROTO * DIM];
__device__ __align__(256) __nv_bfloat16 g_wc[(size_t)DIM * NPROTO];
__device__ __align__(256) __nv_bfloat16 g_S [(size_t)M_ROWS * NPROTO];
__device__ float g_Zp[(size_t)ZCHUNKS * M_ROWS];
__device__ float g_Z[M_ROWS];
__device__ float g_cs[DIM];

// ------------------------- PTX helpers -------------------------------------
static __device__ __forceinline__ uint32_t smem_u32(const void* p) {
    uint32_t a;
    asm("{ .reg .u64 t; cvta.to.shared.u64 t, %1; cvt.u32.u64 %0, t; }"
        : "=r"(a) : "l"(p));
    return a;
}

#define SWZ(o) ((o) ^ (((o) >> 3) & 0x70))

static __device__ __forceinline__ void cpasync16(uint32_t dst, const void* src) {
    asm volatile("cp.async.cg.shared.global [%0], [%1], 16;"
                 :: "r"(dst), "l"(src));
}
// arrive on mbar when all of this thread's prior cp.asyncs have completed
static __device__ __forceinline__ void cp_arrive(uint32_t mbar) {
    asm volatile("cp.async.mbarrier.arrive.noinc.shared::cta.b64 [%0];"
                 :: "r"(mbar) : "memory");
}

static __device__ __forceinline__ void mbar_init(uint32_t a, uint32_t cnt) {
    asm volatile("mbarrier.init.shared.b64 [%0], %1;" :: "r"(a), "r"(cnt) : "memory");
}
static __device__ __forceinline__ void mbar_arrive(uint32_t a) {
    asm volatile("mbarrier.arrive.shared.b64 _, [%0];" :: "r"(a) : "memory");
}
static __device__ __forceinline__ void mbar_wait(uint32_t mbar, uint32_t parity) {
    asm volatile(
        "{\n\t"
        ".reg .pred P;\n\t"
        "WL%=:\n\t"
        "mbarrier.try_wait.parity.acquire.cta.shared::cta.b64 P, [%0], %1, 0x989680;\n\t"
        "@P bra.uni WD%=;\n\t"
        "bra.uni WL%=;\n\t"
        "WD%=:\n\t"
        "}"
        :: "r"(mbar), "r"(parity) : "memory");
}

static __device__ __forceinline__ void ldsm4(uint32_t* r, uint32_t addr) {
    asm volatile("ldmatrix.sync.aligned.m8n8.x4.shared.b16 {%0,%1,%2,%3}, [%4];"
                 : "=r"(r[0]), "=r"(r[1]), "=r"(r[2]), "=r"(r[3])
                 : "r"(addr));
}

static __device__ __forceinline__ void mma16816(float* d, const uint32_t* a,
                                                uint32_t b0, uint32_t b1) {
    asm volatile(
        "mma.sync.aligned.m16n8k16.row.col.f32.bf16.bf16.f32 "
        "{%0,%1,%2,%3}, {%4,%5,%6,%7}, {%8,%9}, {%0,%1,%2,%3};"
        : "+f"(d[0]), "+f"(d[1]), "+f"(d[2]), "+f"(d[3])
        : "r"(a[0]), "r"(a[1]), "r"(a[2]), "r"(a[3]), "r"(b0), "r"(b1));
}

static __device__ __forceinline__ uint32_t pack_bf16x2(float lo, float hi) {
    uint32_t r;
    asm("cvt.rn.bf16x2.f32 %0, %1, %2;" : "=r"(r) : "f"(hi), "f"(lo));
    return r;
}

// ------------------------- small prep kernels ------------------------------
__global__ void k_cvt_x(const float* __restrict__ in) {
    int n = M_ROWS * DIM / 4;
    const float4* p = reinterpret_cast<const float4*>(in);
    uint2* q = reinterpret_cast<uint2*>(g_xb);
    for (int i = blockIdx.x * blockDim.x + threadIdx.x; i < n;
         i += gridDim.x * blockDim.x) {
        float4 v = p[i];
        uint2 o;
        o.x = pack_bf16x2(v.x, v.y);
        o.y = pack_bf16x2(v.z, v.w);
        q[i] = o;
    }
}
__global__ void k_cvt_wl(const float* __restrict__ in) {
    int n = NPROTO * DIM / 4;
    const float4* p = reinterpret_cast<const float4*>(in);
    uint2* q = reinterpret_cast<uint2*>(g_wl);
    for (int i = blockIdx.x * blockDim.x + threadIdx.x; i < n;
         i += gridDim.x * blockDim.x) {
        float4 v = p[i];
        uint2 o;
        o.x = pack_bf16x2(v.x, v.y);
        o.y = pack_bf16x2(v.z, v.w);
        q[i] = o;
    }
}
// per-d: fp32 colsum over 4096 prototypes + bf16 convert
__global__ void k_wc_prep(const float* __restrict__ wc) {
    int d = blockIdx.x;
    int t = threadIdx.x;
    float s = 0.0f;
    const float4* src = reinterpret_cast<const float4*>(wc + (size_t)d * NPROTO);
    uint2* dst = reinterpret_cast<uint2*>(g_wc + (size_t)d * NPROTO);
    for (int i = t; i < NPROTO / 4; i += 256) {
        float4 v = src[i];
        s += (v.x + v.y) + (v.z + v.w);
        uint2 o;
        o.x = pack_bf16x2(v.x, v.y);
        o.y = pack_bf16x2(v.z, v.w);
        dst[i] = o;
    }
    __shared__ float red[8];
    for (int o = 16; o; o >>= 1) s += __shfl_xor_sync(0xFFFFFFFFu, s, o);
    if ((t & 31) == 0) red[t >> 5] = s;
    __syncthreads();
    if (t < 32) {
        float v = (t < 8) ? red[t] : 0.0f;
        for (int o = 4; o; o >>= 1) v += __shfl_xor_sync(0xFFFFFFFFu, v, o);
        if (t == 0) g_cs[d] = v;
    }
}
// Z[r] = sum over ZCHUNKS partials (deterministic fixed order)
__global__ void k_zreduce() {
    int r = blockIdx.x * blockDim.x + threadIdx.x;
    float s = 0.0f;
#pragma unroll 8
    for (int c = 0; c < ZCHUNKS; c++) s += g_Zp[(size_t)c * M_ROWS + r];
    g_Z[r] = s;
}

// ------------------------- main HMMA GEMM ----------------------------------
// MODE 1: A=g_xb [16384,768], B=g_wl [4096,768];
//         epi: g_S = bf16(expm1(beta*acc)), partial row sums -> g_Zp
// MODE 2: A=g_S [16384,4096], B=g_wc [768,4096];
//         epi: out = (g_cs + acc)/(4096+Z)
template <int MODE>
__global__ void __launch_bounds__(256, 2) gemm_mma(float* __restrict__ out) {
    constexpr int ldA = (MODE == 1) ? DIM : NPROTO;
    constexpr int ldB = (MODE == 1) ? DIM : NPROTO;
    constexpr int nK  = (MODE == 1) ? DIM / KC : NPROTO / KC;   // 12 / 64
    const __nv_bfloat16* A = (MODE == 1) ? g_xb : g_S;
    const __nv_bfloat16* B = (MODE == 1) ? g_wl : g_wc;

    extern __shared__ char dsm[];
    __shared__ __align__(8) uint64_t s_full[STAGES];
    __shared__ __align__(8) uint64_t s_empty[STAGES];
    const uint32_t base = (smem_u32(dsm) + 1023u) & ~1023u;
    const uint32_t fullb  = smem_u32(&s_full[0]);
    const uint32_t emptyb = smem_u32(&s_empty[0]);

    const int tid = threadIdx.x;
    const int l   = tid & 31;
    const int wid = tid >> 5;
    const int wm  = wid >> 2;     // 0..1  (64-row slab)
    const int wn  = wid & 3;      // 0..3  (32-col slab)
    const int m0  = blockIdx.y * TILE_M;
    const int n0  = blockIdx.x * TILE_N;

    if (tid < STAGES) {
        mbar_init(fullb  + tid * 8, 256);   // per-thread cp-arrive
        mbar_init(emptyb + tid * 8, 8);     // one arrive per warp
    }
    __syncthreads();

    // ---- cp.async source pointers / dest offsets
    const int ld_r   = tid >> 3;          // 0..31
    const int ld_seg = tid & 7;           // 16B segment in 128B row
    const __nv_bfloat16* Ag = A + (size_t)(m0 + ld_r) * ldA + ld_seg * 8;
    const __nv_bfloat16* Bg = B + (size_t)(n0 + ld_r) * ldB + ld_seg * 8;
    uint32_t dA[4];
#pragma unroll
    for (int s = 0; s < 4; s++)
        dA[s] = SWZ((ld_r + s * 32) * 128 + ld_seg * 16);

    auto fill = [&](int kk, int st) {
        const uint32_t sS = base + st * STAGE_BYTES;
        const __nv_bfloat16* a = Ag + kk * KC;
        const __nv_bfloat16* b = Bg + kk * KC;
#pragma unroll
        for (int s = 0; s < 4; s++)
            cpasync16(sS + dA[s], a + (size_t)(s * 32) * ldA);
#pragma unroll
        for (int s = 0; s < 4; s++)
            cpasync16(sS + STAGE_A + dA[s], b + (size_t)(s * 32) * ldB);
        cp_arrive(fullb + st * 8);
    };

    float acc[4][4][4];
#pragma unroll
    for (int i = 0; i < 4; i++)
#pragma unroll
        for (int j = 0; j < 4; j++)
#pragma unroll
            for (int q = 0; q < 4; q++) acc[i][j][q] = 0.0f;

    // ---- ldmatrix addressing: SWZ(row*128 + d) = row*128 + (d ^ ((row&7)<<4))
    const int a_row = wm * 64 + (l & 15);                       // + mf*16
    const int b_row = wn * 32 + ((l >> 3) & 1) * 8 + (l & 7);   // + nh*16
    const int kb    = (l >> 4) * 16;                            // 16B k-half
    const uint32_t Ta = (uint32_t)((a_row & 7) << 4);
    const uint32_t Tb = (uint32_t)((b_row & 7) << 4);
    uint32_t aoff[4], boff[2];
#pragma unroll
    for (int mf = 0; mf < 4; mf++) aoff[mf] = (a_row + mf * 16) * 128;
#pragma unroll
    for (int nh = 0; nh < 2; nh++) boff[nh] = STAGE_A + (b_row + nh * 16) * 128;
    uint32_t dka[4], dkb[4];
#pragma unroll
    for (int ks = 0; ks < 4; ks++) {
        dka[ks] = (uint32_t)(kb + ks * 32) ^ Ta;
        dkb[ks] = (uint32_t)(kb + ks * 32) ^ Tb;
    }

    // prologue: fill tiles 0,1 into stages 0,1 (empty by construction)
    fill(0, 0);
    fill(1, 1);

    uint32_t af[2][4][4];
    uint32_t bf[2][2][4];

    int st = 0, trip = 0;
    for (int k = 0; k < nK; k++) {
        // refill stage (st+2)%3 with tile k+2 (guarded by its empty barrier)
        const int kf = k + 2;
        if (kf < nK) {
            int stf = st + 2; if (stf >= STAGES) stf -= STAGES;
            if (k >= 1) {
                int eph = (st == 0) ? ((trip - 1) & 1) : (trip & 1);
                mbar_wait(emptyb + stf * 8, (uint32_t)eph);
            }
            fill(kf, stf);
        }

        mbar_wait(fullb + st * 8, (uint32_t)(trip & 1));

        const uint32_t sS = base + st * STAGE_BYTES;

        // prefetch ks=0 fragments
#pragma unroll
        for (int mf = 0; mf < 4; mf++) ldsm4(af[0][mf], sS + aoff[mf] + dka[0]);
#pragma unroll
        for (int nh = 0; nh < 2; nh++) ldsm4(bf[0][nh], sS + boff[nh] + dkb[0]);

#pragma unroll
        for (int ks = 0; ks < 4; ks++) {
            const int cur = ks & 1, nxt = cur ^ 1;
            if (ks < 3) {
#pragma unroll
                for (int mf = 0; mf < 4; mf++)
                    ldsm4(af[nxt][mf], sS + aoff[mf] + dka[ks + 1]);
#pragma unroll
                for (int nh = 0; nh < 2; nh++)
                    ldsm4(bf[nxt][nh], sS + boff[nh] + dkb[ks + 1]);
            }
#pragma unroll
            for (int mf = 0; mf < 4; mf++)
#pragma unroll
                for (int nf = 0; nf < 4; nf++)
                    mma16816(acc[mf][nf], af[cur][mf],
                             bf[cur][nf >> 1][nf & 1],
                             bf[cur][nf >> 1][2 + (nf & 1)]);
        }

        if (l == 0) mbar_arrive(emptyb + st * 8);   // this warp done with stage
        if (++st == STAGES) { st = 0; trip++; }
    }

    // ------------------------- epilogue -------------------------------------
    const int col0 = n0 + wn * 32 + (l & 3) * 2;      // + nf*8
    const int row0 = m0 + wm * 64 + (l >> 2);         // + mf*16 (+8)

    if constexpr (MODE == 1) {
        const int zc = blockIdx.x * 4 + wn;           // 0..127
#pragma unroll
        for (int mf = 0; mf < 4; mf++) {
            int r = row0 + mf * 16;
            float slo = 0.0f, shi = 0.0f;
#pragma unroll
            for (int nf = 0; nf < 4; nf++) {
                int c = col0 + nf * 8;
                float e0 = __expf(acc[mf][nf][0] * BETA_F) - 1.0f;
                float e1 = __expf(acc[mf][nf][1] * BETA_F) - 1.0f;
                float e2 = __expf(acc[mf][nf][2] * BETA_F) - 1.0f;
                float e3 = __expf(acc[mf][nf][3] * BETA_F) - 1.0f;
                slo += e0 + e1;
                shi += e2 + e3;
                uint32_t p01 = pack_bf16x2(e0, e1);
                uint32_t p23 = pack_bf16x2(e2, e3);
                *reinterpret_cast<uint32_t*>(g_S + (size_t)r * NPROTO + c) = p01;
                *reinterpret_cast<uint32_t*>(g_S + (size_t)(r + 8) * NPROTO + c) = p23;
            }
            // reduce 32-col partial over the 4 lanes sharing this row (l&3)
            slo += __shfl_xor_sync(0xFFFFFFFFu, slo, 1);
            slo += __shfl_xor_sync(0xFFFFFFFFu, slo, 2);
            shi += __shfl_xor_sync(0xFFFFFFFFu, shi, 1);
            shi += __shfl_xor_sync(0xFFFFFFFFu, shi, 2);
            if ((l & 3) == 0) {
                g_Zp[(size_t)zc * M_ROWS + r]     = slo;
                g_Zp[(size_t)zc * M_ROWS + r + 8] = shi;
            }
        }
    } else {
        float cs0[4], cs1[4];
#pragma unroll
        for (int nf = 0; nf < 4; nf++) {
            cs0[nf] = __ldg(&g_cs[col0 + nf * 8]);
            cs1[nf] = __ldg(&g_cs[col0 + nf * 8 + 1]);
        }
#pragma unroll
        for (int mf = 0; mf < 4; mf++) {
            int r = row0 + mf * 16;
            float iz0 = 1.0f / (4096.0f + __ldg(&g_Z[r]));
            float iz1 = 1.0f / (4096.0f + __ldg(&g_Z[r + 8]));
#pragma unroll
            for (int nf = 0; nf < 4; nf++) {
                int c = col0 + nf * 8;
                float2 v0, v1;
                v0.x = (cs0[nf] + acc[mf][nf][0]) * iz0;
                v0.y = (cs1[nf] + acc[mf][nf][1]) * iz0;
                v1.x = (cs0[nf] + acc[mf][nf][2]) * iz1;
                v1.y = (cs1[nf] + acc[mf][nf][3]) * iz1;
                *reinterpret_cast<float2*>(out + (size_t)r * DIM + c) = v0;
                *reinterpret_cast<float2*>(out + (size_t)(r + 8) * DIM + c) = v1;
            }
        }
    }
}

// ------------------------- launch ------------------------------------------
extern "C" void kernel_launch(void* const* d_in, const int* in_sizes, int n_in,
                              void* d_out, int out_size) {
    (void)in_sizes; (void)n_in; (void)out_size;
    const float* x  = (const float*)d_in[0];
    const float* wl = (const float*)d_in[1];
    const float* wc = (const float*)d_in[2];
    float* out = (float*)d_out;

    cudaFuncSetAttribute(gemm_mma<1>, cudaFuncAttributeMaxDynamicSharedMemorySize,
                         SMEM_DYN);
    cudaFuncSetAttribute(gemm_mma<2>, cudaFuncAttributeMaxDynamicSharedMemorySize,
                         SMEM_DYN);

    k_cvt_x <<<2048, 256>>>(x);
    k_cvt_wl<<<1024, 256>>>(wl);
    k_wc_prep<<<DIM, 256>>>(wc);

    dim3 g1(NPROTO / TILE_N, M_ROWS / TILE_M);   // (32, 128)
    gemm_mma<1><<<g1, 256, SMEM_DYN>>>(nullptr);

    k_zreduce<<<M_ROWS / 256, 256>>>();

    dim3 g2(DIM / TILE_N, M_ROWS / TILE_M);      // (6, 128)
    gemm_mma<2><<<g2, 256, SMEM_DYN>>>(out);
}